// round 10
// baseline (speedup 1.0000x reference)
#include <cuda_runtime.h>
#include <cuda_fp16.h>
#include <cstdint>

#define NB 4
#define NS 2048
#define NE 128
#define NH 16
#define ND 8
#define NBH (NB * NH)

// Staged head data (written by qgen, read by attn)
// g_kh holds fp16 pairs of (sqrt(log2e/sqrt(8)) * q)  -> score MMA operands (A and B)
// g_vp holds pair-packed fp16 of (raw v * mask)       -> PV MMA B operand
__device__ uint32_t g_kh[NBH * NS * 4];     // 2 MB
__device__ uint32_t g_vp[NBH * (NS/2) * 8]; // 2 MB
__device__ float    g_attn[NB * NS * NE];   // 4 MB

__device__ __forceinline__ uint32_t ex2h2(uint32_t x) {
    uint32_t r; asm("ex2.approx.f16x2 %0,%1;" : "=r"(r) : "r"(x)); return r;
}
__device__ __forceinline__ uint32_t hfma2(uint32_t a, uint32_t b, uint32_t c) {
    uint32_t r; asm("fma.rn.f16x2 %0,%1,%2,%3;" : "=r"(r) : "r"(a), "r"(b), "r"(c)); return r;
}
// score MMA: m16n8k8, fp16 accumulate -> D already packed f16x2
__device__ __forceinline__ void mma16808h(uint32_t& dlo, uint32_t& dhi,
                                          uint32_t a0, uint32_t a1, uint32_t b0) {
    asm volatile("mma.sync.aligned.m16n8k8.row.col.f16.f16.f16.f16 "
                 "{%0,%1},{%2,%3},{%4},{%5,%5};"
                 : "=r"(dlo), "=r"(dhi)
                 : "r"(a0), "r"(a1), "r"(b0), "r"(0u));
}
// PV MMA: m16n8k16, fp16 accumulate (C=D in registers)
__device__ __forceinline__ void mma16816h(uint32_t& d0, uint32_t& d1,
                                          uint32_t a0, uint32_t a1, uint32_t a2, uint32_t a3,
                                          uint32_t b0, uint32_t b1) {
    asm volatile("mma.sync.aligned.m16n8k16.row.col.f16.f16.f16.f16 "
                 "{%0,%1},{%2,%3,%4,%5},{%6,%7},{%0,%1};"
                 : "+r"(d0), "+r"(d1)
                 : "r"(a0), "r"(a1), "r"(a2), "r"(a3), "r"(b0), "r"(b1));
}

// ---------------------------------------------------------------------------
// Kernel A: q = cumprod(cos(x+theta)); emit sqrtCL-scaled fp16 pairs
// (score operands) + mask-folded pair-packed V.
// ---------------------------------------------------------------------------
__global__ void __launch_bounds__(128) qgen_kernel(const float* __restrict__ x,
                                                   const float* __restrict__ theta,
                                                   const int* __restrict__ mask) {
    int r = blockIdx.x * blockDim.x + threadIdx.x;   // r = bh*NS + s
    if (r >= NBH * NS) return;
    int s  = r & (NS - 1);
    int bh = r >> 11;
    int h  = bh & (NH - 1);
    int b  = bh >> 4;

    const float4* xp = (const float4*)(x + ((size_t)(b * NS + s) * NE + h * ND));
    float4 x0 = xp[0], x1 = xp[1];

    float v[8];
    float p;
    p  = cosf(x0.x + theta[0]);  v[0] = p;
    p *= cosf(x0.y + theta[1]);  v[1] = p;
    p *= cosf(x0.z + theta[2]);  v[2] = p;
    p *= cosf(x0.w + theta[3]);  v[3] = p;
    p *= cosf(x1.x + theta[4]);  v[4] = p;
    p *= cosf(x1.y + theta[5]);  v[5] = p;
    p *= cosf(x1.z + theta[6]);  v[6] = p;
    p *= cosf(x1.w + theta[7]);  v[7] = p;

    // sqrt(log2(e)/sqrt(8)) folded into BOTH score operands
    const float CLS = 0.71421430302f;   // sqrt(0.51010205144336435)
    uint32_t hw[4];
#pragma unroll
    for (int j = 0; j < 4; ++j) {
        __half h0 = __float2half_rn(v[2 * j] * CLS);
        __half h1 = __float2half_rn(v[2 * j + 1] * CLS);
        hw[j] = (uint32_t)__half_as_ushort(h0) | ((uint32_t)__half_as_ushort(h1) << 16);
    }
    ((uint4*)g_kh)[r] = make_uint4(hw[0], hw[1], hw[2], hw[3]);

    // pair-packed V with mask folded: g_vp[bh][s/2][n] = half2{v*m (even), (odd)}
    float m = (float)mask[b * NS + s];
    uint16_t* vp16 = (uint16_t*)g_vp;
    size_t base = (((size_t)bh * (NS / 2) + (s >> 1)) * 8) * 2 + (s & 1);
#pragma unroll
    for (int n = 0; n < 8; ++n)
        vp16[base + 2 * n] = __half_as_ushort(__float2half_rn(v[n] * m));
}

// ---------------------------------------------------------------------------
// Kernel B: HMMA flash attention, NO f32-accumulate MMAs.
// Per 16q x 16k iter: 3x LDS.64 + 2 score HMMA (k8,f16) -> ex2.f16x2
//   -> PV HMMA (k16, f16 acc) + den via 4x HFMA2 (P * mask, f16x2).
// Both PV and den accumulators promoted to f32 every 4 iters (64 keys).
// ---------------------------------------------------------------------------
__global__ void __launch_bounds__(256) attn_kernel(const int* __restrict__ mask) {
    extern __shared__ char smem[];
    uint32_t* sKh = (uint32_t*)smem;                    // 32 KB, [blk][r][cp][half]
    uint32_t* sVp = sKh + NS * 4;                       // 32 KB, [blk][n][cp][half]
    uint32_t* sVm = sVp + NS * 4;                       //  4 KB, [blk][cp][half]

    int tid = threadIdx.x;
    int bh = blockIdx.x;
    int b  = bh >> 4;
    int h  = bh & (NH - 1);

    {   // stage with block-interleaved re-layout
        const uint4* gh = (const uint4*)(g_kh + (size_t)bh * NS * 4);
        const uint4* gv = (const uint4*)(g_vp + (size_t)bh * (NS / 2) * 8);
        for (int s = tid; s < NS; s += 256) {
            uint4 k = gh[s];
            uint32_t* d = sKh + ((s >> 4) * 64 + (s & 7) * 8 + ((s >> 3) & 1));
            d[0] = k.x; d[2] = k.y; d[4] = k.z; d[6] = k.w;
        }
        for (int i = tid; i < NS; i += 256) {
            uint4 v = gv[i];
            int p = i >> 1;
            uint32_t* d = sVp + ((p >> 3) * 64 + (i & 1) * 32 + (p & 3) * 2 + ((p >> 2) & 1));
            d[0] = v.x; d[8] = v.y; d[16] = v.z; d[24] = v.w;
        }
        const int* mrow = mask + b * NS;
        for (int i = tid; i < NS / 2; i += 256) {
            __half m0 = __float2half_rn((float)mrow[2 * i]);
            __half m1 = __float2half_rn((float)mrow[2 * i + 1]);
            uint32_t pk = (uint32_t)__half_as_ushort(m0) | ((uint32_t)__half_as_ushort(m1) << 16);
            sVm[(i >> 3) * 8 + (i & 3) * 2 + ((i >> 2) & 1)] = pk;
        }
    }
    __syncthreads();

    int warp = tid >> 5, lane = tid & 31;
    int r0 = lane >> 2, cp = lane & 3;
    int qw = blockIdx.y * 128 + warp * 16;              // warp's first query

    const uint32_t* gkh = g_kh + (size_t)bh * NS * 4;
    uint32_t A0 = gkh[(qw + r0) * 4 + cp];
    uint32_t A1 = gkh[(qw + r0 + 8) * 4 + cp];

    float of0 = 0.f, of1 = 0.f, of2 = 0.f, of3 = 0.f;   // promoted num (f32)
    float fd0 = 0.f, fd1 = 0.f;                          // promoted den (f32)

    const int off  = r0 * 8 + cp * 2;
    const int offm = cp * 2;

#pragma unroll 1
    for (int ob = 0; ob < NS / 64; ++ob) {               // 32 outer chunks
        uint32_t oh0 = 0u, oh1 = 0u;                     // f16x2 PV accumulators
        uint32_t dA = 0u, dB = 0u;                       // f16x2 den accumulators
#pragma unroll
        for (int ii = 0; ii < 4; ++ii) {                 // 4 iters = 64 keys
            int it = ob * 4 + ii;
            uint2 kk = *(const uint2*)(sKh + it * 64 + off);
            uint2 vv = *(const uint2*)(sVp + it * 64 + off);
            uint2 mm = *(const uint2*)(sVm + it * 8 + offm);

            uint32_t d0l, d0h, d1l, d1h;
            mma16808h(d0l, d0h, A0, A1, kk.x);           // keys 0-7 of block
            mma16808h(d1l, d1h, A0, A1, kk.y);           // keys 8-15

            uint32_t pe0 = ex2h2(d0l);   // row r0,   keys 2cp..2cp+1
            uint32_t pe1 = ex2h2(d0h);   // row r0+8
            uint32_t po0 = ex2h2(d1l);   // row r0,   keys 8+2cp..
            uint32_t po1 = ex2h2(d1h);   // row r0+8

            mma16816h(oh0, oh1, pe0, pe1, po0, po1, vv.x, vv.y);  // numerator
            dA = hfma2(pe0, mm.x, dA);                   // den row r0
            dA = hfma2(po0, mm.y, dA);
            dB = hfma2(pe1, mm.x, dB);                   // den row r0+8
            dB = hfma2(po1, mm.y, dB);
        }
        // promote chunk to f32
        float2 f0 = __half22float2(*(__half2*)&oh0);     // row r0: cols 2cp, 2cp+1
        float2 f1 = __half22float2(*(__half2*)&oh1);     // row r0+8
        of0 += f0.x; of1 += f0.y; of2 += f1.x; of3 += f1.y;
        float2 a = __half22float2(*(__half2*)&dA);
        float2 c = __half22float2(*(__half2*)&dB);
        fd0 += a.x + a.y;
        fd1 += c.x + c.y;
    }

    // den: reduce across the quad (cp lanes hold disjoint key subsets)
    fd0 += __shfl_xor_sync(0xffffffffu, fd0, 1); fd0 += __shfl_xor_sync(0xffffffffu, fd0, 2);
    fd1 += __shfl_xor_sync(0xffffffffu, fd1, 1); fd1 += __shfl_xor_sync(0xffffffffu, fd1, 2);
    float i0 = __fdividef(1.0f, fmaxf(fd0, 1e-30f));
    float i1 = __fdividef(1.0f, fmaxf(fd1, 1e-30f));

    size_t col = (size_t)h * ND + 2 * cp;
    float2* out0 = (float2*)(g_attn + ((size_t)(b * NS + qw + r0) * NE + col));
    float2* out1 = (float2*)(g_attn + ((size_t)(b * NS + qw + r0 + 8) * NE + col));
    *out0 = make_float2(of0 * i0, of1 * i0);
    *out1 = make_float2(of2 * i1, of3 * i1);
}

// ---------------------------------------------------------------------------
// Kernel C: out[r, e] = sum_f attn[r, f] * w_out[e, f]
// ---------------------------------------------------------------------------
__global__ void __launch_bounds__(256) out_kernel(const float* __restrict__ w,
                                                  float* __restrict__ out) {
    extern __shared__ float sW[];   // [128][132] padded transpose
    for (int i = threadIdx.x; i < NE * NE; i += 256) {
        int e = i >> 7;
        int f = i & 127;
        sW[f * 132 + e] = w[i];
    }
    __syncthreads();

    int warp = threadIdx.x >> 5;
    int lane = threadIdx.x & 31;
    int rbase = blockIdx.x * 64 + warp * 8;

    for (int k = 0; k < 8; ++k) {
        int r = rbase + k;
        const float4* arow = (const float4*)(g_attn + (size_t)r * NE);
        float4 acc = make_float4(0.f, 0.f, 0.f, 0.f);
#pragma unroll 4
        for (int fi = 0; fi < 32; ++fi) {
            float4 a4 = arow[fi];
            int f = fi * 4;
            float4 w0 = *(const float4*)&sW[(f + 0) * 132 + lane * 4];
            acc.x = fmaf(a4.x, w0.x, acc.x);
            acc.y = fmaf(a4.x, w0.y, acc.y);
            acc.z = fmaf(a4.x, w0.z, acc.z);
            acc.w = fmaf(a4.x, w0.w, acc.w);
            float4 w1 = *(const float4*)&sW[(f + 1) * 132 + lane * 4];
            acc.x = fmaf(a4.y, w1.x, acc.x);
            acc.y = fmaf(a4.y, w1.y, acc.y);
            acc.z = fmaf(a4.y, w1.z, acc.z);
            acc.w = fmaf(a4.y, w1.w, acc.w);
            float4 w2 = *(const float4*)&sW[(f + 2) * 132 + lane * 4];
            acc.x = fmaf(a4.z, w2.x, acc.x);
            acc.y = fmaf(a4.z, w2.y, acc.y);
            acc.z = fmaf(a4.z, w2.z, acc.z);
            acc.w = fmaf(a4.z, w2.w, acc.w);
            float4 w3 = *(const float4*)&sW[(f + 3) * 132 + lane * 4];
            acc.x = fmaf(a4.w, w3.x, acc.x);
            acc.y = fmaf(a4.w, w3.y, acc.y);
            acc.z = fmaf(a4.w, w3.z, acc.z);
            acc.w = fmaf(a4.w, w3.w, acc.w);
        }
        *(float4*)(out + (size_t)r * NE + lane * 4) = acc;
    }
}

// ---------------------------------------------------------------------------
extern "C" void kernel_launch(void* const* d_in, const int* in_sizes, int n_in,
                              void* d_out, int out_size) {
    const float* x     = (const float*)d_in[0];
    const float* theta = (const float*)d_in[1];
    const float* w     = (const float*)d_in[2];
    const int*   mask  = (const int*)d_in[3];
    float*       out   = (float*)d_out;

    qgen_kernel<<<(NBH * NS) / 128, 128>>>(x, theta, mask);

    int smB = NS * 4 * 4 * 2 + (NS / 2) * 4;   // 64 KB K/V + 4 KB mask = 69632 B
    cudaFuncSetAttribute(attn_kernel, cudaFuncAttributeMaxDynamicSharedMemorySize, smB);
    attn_kernel<<<dim3(NBH, NS / 128), 256, smB>>>(mask);

    int smC = 128 * 132 * 4;
    cudaFuncSetAttribute(out_kernel, cudaFuncAttributeMaxDynamicSharedMemorySize, smC);
    out_kernel<<<(NB * NS) / 64, 256, smC>>>(w, out);
}

// round 11
// speedup vs baseline: 1.0461x; 1.0461x over previous
#include <cuda_runtime.h>
#include <cuda_fp16.h>
#include <cstdint>

#define NB 4
#define NS 2048
#define NE 128
#define NH 16
#define ND 8
#define NBH (NB * NH)
#define KH 1024            // keys per CTA (half of NS)

// Staged head data (written by qgen, read by attn)
__device__ uint32_t g_kh[NBH * NS * 4];     // 2 MB fp16x2 CLS-scaled q/k
__device__ uint32_t g_vp[NBH * (NS/2) * 8]; // 2 MB pair-packed v*mask
__device__ float    g_num[2][NB * NS * NE]; // 8 MB partial numerators
__device__ float    g_den[2][NB * NS * NH]; // 1 MB partial denominators
__device__ float    g_attn[NB * NS * NE];   // 4 MB combined attn

__device__ __forceinline__ uint32_t ex2h2(uint32_t x) {
    uint32_t r; asm("ex2.approx.f16x2 %0,%1;" : "=r"(r) : "r"(x)); return r;
}
// score MMA: m16n8k8, fp16 accumulate -> D already packed f16x2
__device__ __forceinline__ void mma16808h(uint32_t& dlo, uint32_t& dhi,
                                          uint32_t a0, uint32_t a1, uint32_t b0) {
    asm volatile("mma.sync.aligned.m16n8k8.row.col.f16.f16.f16.f16 "
                 "{%0,%1},{%2,%3},{%4},{%5,%5};"
                 : "=r"(dlo), "=r"(dhi)
                 : "r"(a0), "r"(a1), "r"(b0), "r"(0u));
}
__device__ __forceinline__ void mma16816(float c[4],
                                         uint32_t a0, uint32_t a1, uint32_t a2, uint32_t a3,
                                         uint32_t b0, uint32_t b1) {
    asm volatile("mma.sync.aligned.m16n8k16.row.col.f32.f16.f16.f32 "
                 "{%0,%1,%2,%3},{%4,%5,%6,%7},{%8,%9},{%0,%1,%2,%3};"
                 : "+f"(c[0]), "+f"(c[1]), "+f"(c[2]), "+f"(c[3])
                 : "r"(a0), "r"(a1), "r"(a2), "r"(a3), "r"(b0), "r"(b1));
}

// ---------------------------------------------------------------------------
// Kernel A: q = cumprod(cos(x+theta)); emit sqrtCL-scaled fp16 pairs
// (score operands) + mask-folded pair-packed V.
// ---------------------------------------------------------------------------
__global__ void __launch_bounds__(128) qgen_kernel(const float* __restrict__ x,
                                                   const float* __restrict__ theta,
                                                   const int* __restrict__ mask) {
    int r = blockIdx.x * blockDim.x + threadIdx.x;   // r = bh*NS + s
    if (r >= NBH * NS) return;
    int s  = r & (NS - 1);
    int bh = r >> 11;
    int h  = bh & (NH - 1);
    int b  = bh >> 4;

    const float4* xp = (const float4*)(x + ((size_t)(b * NS + s) * NE + h * ND));
    float4 x0 = xp[0], x1 = xp[1];

    float v[8];
    float p;
    p  = cosf(x0.x + theta[0]);  v[0] = p;
    p *= cosf(x0.y + theta[1]);  v[1] = p;
    p *= cosf(x0.z + theta[2]);  v[2] = p;
    p *= cosf(x0.w + theta[3]);  v[3] = p;
    p *= cosf(x1.x + theta[4]);  v[4] = p;
    p *= cosf(x1.y + theta[5]);  v[5] = p;
    p *= cosf(x1.z + theta[6]);  v[6] = p;
    p *= cosf(x1.w + theta[7]);  v[7] = p;

    // sqrt(log2(e)/sqrt(8)) folded into BOTH score operands
    const float CLS = 0.71421430302f;   // sqrt(0.51010205144336435)
    uint32_t hw[4];
#pragma unroll
    for (int j = 0; j < 4; ++j) {
        __half h0 = __float2half_rn(v[2 * j] * CLS);
        __half h1 = __float2half_rn(v[2 * j + 1] * CLS);
        hw[j] = (uint32_t)__half_as_ushort(h0) | ((uint32_t)__half_as_ushort(h1) << 16);
    }
    ((uint4*)g_kh)[r] = make_uint4(hw[0], hw[1], hw[2], hw[3]);

    // pair-packed V with mask folded: g_vp[bh][s/2][n] = half2{v*m (even), (odd)}
    float m = (float)mask[b * NS + s];
    uint16_t* vp16 = (uint16_t*)g_vp;
    size_t base = (((size_t)bh * (NS / 2) + (s >> 1)) * 8) * 2 + (s & 1);
#pragma unroll
    for (int n = 0; n < 8; ++n)
        vp16[base + 2 * n] = __half_as_ushort(__float2half_rn(v[n] * m));
}

// ---------------------------------------------------------------------------
// Kernel B: HMMA flash attention, key-split for occupancy.
// CTA = (head bh, 128-query tile, key half kh). Stages only 1024 keys
// -> 34 KB SMEM -> 6 CTAs/SM (12 warps/SMSP) for latency hiding.
// Inner loop identical to the best (R9) version.
// Writes raw partial num/den; combine_kernel normalizes.
// ---------------------------------------------------------------------------
__global__ void __launch_bounds__(256) attn_kernel(const int* __restrict__ mask) {
    extern __shared__ char smem[];
    uint32_t* sKh = (uint32_t*)smem;                    // 16 KB, [blk][r][cp][half]
    uint32_t* sVp = sKh + KH * 4;                       // 16 KB
    uint32_t* sVm = sVp + KH * 4;                       //  2 KB

    int tid = threadIdx.x;
    int bh = blockIdx.x;
    int kh = blockIdx.z;                                // key half
    int b  = bh >> 4;
    int h  = bh & (NH - 1);

    {   // stage this half's keys with block-interleaved re-layout
        const uint4* gh = (const uint4*)(g_kh + ((size_t)bh * NS + kh * KH) * 4);
        const uint4* gv = (const uint4*)(g_vp + ((size_t)bh * (NS / 2) + kh * (KH / 2)) * 8);
        for (int s = tid; s < KH; s += 256) {
            uint4 k = gh[s];
            uint32_t* d = sKh + ((s >> 4) * 64 + (s & 7) * 8 + ((s >> 3) & 1));
            d[0] = k.x; d[2] = k.y; d[4] = k.z; d[6] = k.w;
        }
        for (int i = tid; i < KH; i += 256) {
            uint4 v = gv[i];
            int p = i >> 1;
            uint32_t* d = sVp + ((p >> 3) * 64 + (i & 1) * 32 + (p & 3) * 2 + ((p >> 2) & 1));
            d[0] = v.x; d[8] = v.y; d[16] = v.z; d[24] = v.w;
        }
        const int* mrow = mask + b * NS + kh * KH;
        for (int i = tid; i < KH / 2; i += 256) {
            __half m0 = __float2half_rn((float)mrow[2 * i]);
            __half m1 = __float2half_rn((float)mrow[2 * i + 1]);
            uint32_t pk = (uint32_t)__half_as_ushort(m0) | ((uint32_t)__half_as_ushort(m1) << 16);
            sVm[(i >> 3) * 8 + (i & 3) * 2 + ((i >> 2) & 1)] = pk;
        }
    }
    __syncthreads();

    int warp = tid >> 5, lane = tid & 31;
    int r0 = lane >> 2, cp = lane & 3;
    int qw = blockIdx.y * 128 + warp * 16;              // warp's first query

    const uint32_t* gkh = g_kh + (size_t)bh * NS * 4;
    uint32_t A0 = gkh[(qw + r0) * 4 + cp];
    uint32_t A1 = gkh[(qw + r0 + 8) * 4 + cp];

    float o[4]  = {0.f, 0.f, 0.f, 0.f};     // PV accumulator
    float o2[4] = {0.f, 0.f, 0.f, 0.f};     // den accumulator

    const int off  = r0 * 8 + cp * 2;
    const int offm = cp * 2;

#pragma unroll 4
    for (int it = 0; it < KH / 16; ++it) {
        uint2 kk = *(const uint2*)(sKh + it * 64 + off);   // {bh0, bh1}
        uint2 vv = *(const uint2*)(sVp + it * 64 + off);   // {vb0, vb1}
        uint2 mm = *(const uint2*)(sVm + it * 8 + offm);   // {vm0, vm1}

        uint32_t d0l, d0h, d1l, d1h;
        mma16808h(d0l, d0h, A0, A1, kk.x);                 // keys 0-7 of block
        mma16808h(d1l, d1h, A0, A1, kk.y);                 // keys 8-15

        uint32_t pe0 = ex2h2(d0l);   // row r0,   keys 2cp..2cp+1
        uint32_t pe1 = ex2h2(d0h);   // row r0+8
        uint32_t po0 = ex2h2(d1l);   // row r0,   keys 8+2cp
        uint32_t po1 = ex2h2(d1h);   // row r0+8

        mma16816(o,  pe0, pe1, po0, po1, vv.x, vv.y);      // numerator
        mma16816(o2, pe0, pe1, po0, po1, mm.x, mm.y);      // denominator
    }

    // write raw partials (den identical across cp columns; write once)
    float* nump = g_num[kh];
    size_t col = (size_t)h * ND + 2 * cp;
    float2* out0 = (float2*)(nump + ((size_t)(b * NS + qw + r0) * NE + col));
    float2* out1 = (float2*)(nump + ((size_t)(b * NS + qw + r0 + 8) * NE + col));
    *out0 = make_float2(o[0], o[1]);
    *out1 = make_float2(o[2], o[3]);
    if (cp == 0) {
        g_den[kh][(size_t)(b * NS + qw + r0) * NH + h]     = o2[0];
        g_den[kh][(size_t)(b * NS + qw + r0 + 8) * NH + h] = o2[2];
    }
}

// ---------------------------------------------------------------------------
// Kernel B2: combine halves: attn = (n0+n1) / (d0+d1), one head-row per thread
// ---------------------------------------------------------------------------
__global__ void __launch_bounds__(256) combine_kernel() {
    int i = blockIdx.x * blockDim.x + threadIdx.x;      // i = row*NH + h
    if (i >= NB * NS * NH) return;
    float den = g_den[0][i] + g_den[1][i];
    float inv = __fdividef(1.0f, fmaxf(den, 1e-30f));
    size_t e0 = (size_t)(i >> 4) * NE + (i & 15) * ND;
    const float4* n0 = (const float4*)(g_num[0] + e0);
    const float4* n1 = (const float4*)(g_num[1] + e0);
    float4* ap = (float4*)(g_attn + e0);
    float4 a = n0[0], c = n1[0];
    ap[0] = make_float4((a.x + c.x) * inv, (a.y + c.y) * inv,
                        (a.z + c.z) * inv, (a.w + c.w) * inv);
    a = n0[1]; c = n1[1];
    ap[1] = make_float4((a.x + c.x) * inv, (a.y + c.y) * inv,
                        (a.z + c.z) * inv, (a.w + c.w) * inv);
}

// ---------------------------------------------------------------------------
// Kernel C: out[r, e] = sum_f attn[r, f] * w_out[e, f]
// ---------------------------------------------------------------------------
__global__ void __launch_bounds__(256) out_kernel(const float* __restrict__ w,
                                                  float* __restrict__ out) {
    extern __shared__ float sW[];   // [128][132] padded transpose
    for (int i = threadIdx.x; i < NE * NE; i += 256) {
        int e = i >> 7;
        int f = i & 127;
        sW[f * 132 + e] = w[i];
    }
    __syncthreads();

    int warp = threadIdx.x >> 5;
    int lane = threadIdx.x & 31;
    int rbase = blockIdx.x * 64 + warp * 8;

    for (int k = 0; k < 8; ++k) {
        int r = rbase + k;
        const float4* arow = (const float4*)(g_attn + (size_t)r * NE);
        float4 acc = make_float4(0.f, 0.f, 0.f, 0.f);
#pragma unroll 4
        for (int fi = 0; fi < 32; ++fi) {
            float4 a4 = arow[fi];
            int f = fi * 4;
            float4 w0 = *(const float4*)&sW[(f + 0) * 132 + lane * 4];
            acc.x = fmaf(a4.x, w0.x, acc.x);
            acc.y = fmaf(a4.x, w0.y, acc.y);
            acc.z = fmaf(a4.x, w0.z, acc.z);
            acc.w = fmaf(a4.x, w0.w, acc.w);
            float4 w1 = *(const float4*)&sW[(f + 1) * 132 + lane * 4];
            acc.x = fmaf(a4.y, w1.x, acc.x);
            acc.y = fmaf(a4.y, w1.y, acc.y);
            acc.z = fmaf(a4.y, w1.z, acc.z);
            acc.w = fmaf(a4.y, w1.w, acc.w);
            float4 w2 = *(const float4*)&sW[(f + 2) * 132 + lane * 4];
            acc.x = fmaf(a4.z, w2.x, acc.x);
            acc.y = fmaf(a4.z, w2.y, acc.y);
            acc.z = fmaf(a4.z, w2.z, acc.z);
            acc.w = fmaf(a4.z, w2.w, acc.w);
            float4 w3 = *(const float4*)&sW[(f + 3) * 132 + lane * 4];
            acc.x = fmaf(a4.w, w3.x, acc.x);
            acc.y = fmaf(a4.w, w3.y, acc.y);
            acc.z = fmaf(a4.w, w3.z, acc.z);
            acc.w = fmaf(a4.w, w3.w, acc.w);
        }
        *(float4*)(out + (size_t)r * NE + lane * 4) = acc;
    }
}

// ---------------------------------------------------------------------------
extern "C" void kernel_launch(void* const* d_in, const int* in_sizes, int n_in,
                              void* d_out, int out_size) {
    const float* x     = (const float*)d_in[0];
    const float* theta = (const float*)d_in[1];
    const float* w     = (const float*)d_in[2];
    const int*   mask  = (const int*)d_in[3];
    float*       out   = (float*)d_out;

    qgen_kernel<<<(NBH * NS) / 128, 128>>>(x, theta, mask);

    int smB = KH * 4 * 4 * 2 + (KH / 2) * 4;   // 32 KB K/V + 2 KB mask = 34816 B
    cudaFuncSetAttribute(attn_kernel, cudaFuncAttributeMaxDynamicSharedMemorySize, smB);
    attn_kernel<<<dim3(NBH, NS / 128, 2), 256, smB>>>(mask);

    combine_kernel<<<(NB * NS * NH) / 256, 256>>>();

    int smC = 128 * 132 * 4;
    cudaFuncSetAttribute(out_kernel, cudaFuncAttributeMaxDynamicSharedMemorySize, smC);
    out_kernel<<<(NB * NS) / 64, 256, smC>>>(w, out);
}